// round 10
// baseline (speedup 1.0000x reference)
#include <cuda_runtime.h>
#include <cuda_fp16.h>
#include <math.h>
#include <stdint.h>

#define BB   8
#define WLEN 1000
#define EMB  100
#define CC   50
#define LL   18000

#define WPAD 1024
// H: [b][w][k-halves], 64 halves (128B) per w row; k>=50 and w>=1000 stay zero
__device__ __align__(16) uint32_t g_Hh[BB * WPAD * 32];

// ===========================================================================
// Kernel 1: embedding + conv1d(k=3,same) + tanh -> g_Hh[b][w][k]
// swizzled emb_s: 16B-unit index = row*32 + (e4 ^ ((row>>2)&7)) (conflict-free)
// ===========================================================================
#define CT_W    40
#define CT_ROWS (CT_W + 2)

__device__ __forceinline__ float tanh_fast(float x) {
    float y;
    asm("tanh.approx.f32 %0, %1;" : "=f"(y) : "f"(x));
    return y;
}

__global__ __launch_bounds__(256)
void conv_kernel(const int* __restrict__ x, const float* __restrict__ W_embed,
                 const float* __restrict__ conv_w, const float* __restrict__ conv_b) {
    __shared__ __align__(16) float emb_s[CT_ROWS * 128];
    __shared__ int tok_s[CT_ROWS];
    const int b  = blockIdx.y;
    const int w0 = blockIdx.x * CT_W;
    const int tid = threadIdx.x;

    if (tid < CT_ROWS) {
        int w = w0 - 1 + tid;
        tok_s[tid] = (w >= 0 && w < WLEN) ? x[b * WLEN + w] : -1;
    }
    __syncthreads();
    for (int i = tid; i < CT_ROWS * 25; i += 256) {
        int r = i / 25, g = i - r * 25;
        int t = tok_s[r];
        float4 v = make_float4(0.f, 0.f, 0.f, 0.f);
        if (t >= 0) v = *(const float4*)&W_embed[(long)t * EMB + g * 4];
        *(float4*)&emb_s[(r * 32 + (g ^ ((r >> 2) & 7))) * 4] = v;
    }
    __syncthreads();

    if (tid < 250) {
        const int p = tid / 10, q = tid - p * 10;
        const int wl = q * 4;
        const int sw0 = q & 7, sw1 = (q + 1) & 7;
        const int c0 = 2 * p, c1 = 2 * p + 1;
        float acc[2][4];
        float bias0 = conv_b[c0], bias1 = conv_b[c1];
#pragma unroll
        for (int w = 0; w < 4; w++) { acc[0][w] = bias0; acc[1][w] = bias1; }

        const float4* cw0 = (const float4*)(conv_w + c0 * EMB * 3);
        const float4* cw1 = (const float4*)(conv_w + c1 * EMB * 3);

        for (int g = 0; g < 25; g++) {
            float4 v[6];
#pragma unroll
            for (int r = 0; r < 6; r++) {
                int sw = (r < 4) ? sw0 : sw1;
                v[r] = *(const float4*)&emb_s[((wl + r) * 32 + (g ^ sw)) * 4];
            }
            float4 q0 = cw0[g * 3], q1 = cw0[g * 3 + 1], q2 = cw0[g * 3 + 2];
#pragma unroll
            for (int w = 0; w < 4; w++) {
                acc[0][w] = fmaf(v[w].x, q0.x, acc[0][w]);
                acc[0][w] = fmaf(v[w + 1].x, q0.y, acc[0][w]);
                acc[0][w] = fmaf(v[w + 2].x, q0.z, acc[0][w]);
                acc[0][w] = fmaf(v[w].y, q0.w, acc[0][w]);
                acc[0][w] = fmaf(v[w + 1].y, q1.x, acc[0][w]);
                acc[0][w] = fmaf(v[w + 2].y, q1.y, acc[0][w]);
                acc[0][w] = fmaf(v[w].z, q1.z, acc[0][w]);
                acc[0][w] = fmaf(v[w + 1].z, q1.w, acc[0][w]);
                acc[0][w] = fmaf(v[w + 2].z, q2.x, acc[0][w]);
                acc[0][w] = fmaf(v[w].w, q2.y, acc[0][w]);
                acc[0][w] = fmaf(v[w + 1].w, q2.z, acc[0][w]);
                acc[0][w] = fmaf(v[w + 2].w, q2.w, acc[0][w]);
            }
            q0 = cw1[g * 3]; q1 = cw1[g * 3 + 1]; q2 = cw1[g * 3 + 2];
#pragma unroll
            for (int w = 0; w < 4; w++) {
                acc[1][w] = fmaf(v[w].x, q0.x, acc[1][w]);
                acc[1][w] = fmaf(v[w + 1].x, q0.y, acc[1][w]);
                acc[1][w] = fmaf(v[w + 2].x, q0.z, acc[1][w]);
                acc[1][w] = fmaf(v[w].y, q0.w, acc[1][w]);
                acc[1][w] = fmaf(v[w + 1].y, q1.x, acc[1][w]);
                acc[1][w] = fmaf(v[w + 2].y, q1.y, acc[1][w]);
                acc[1][w] = fmaf(v[w].z, q1.z, acc[1][w]);
                acc[1][w] = fmaf(v[w + 1].z, q1.w, acc[1][w]);
                acc[1][w] = fmaf(v[w + 2].z, q2.x, acc[1][w]);
                acc[1][w] = fmaf(v[w].w, q2.y, acc[1][w]);
                acc[1][w] = fmaf(v[w + 1].w, q2.z, acc[1][w]);
                acc[1][w] = fmaf(v[w + 2].w, q2.w, acc[1][w]);
            }
        }
#pragma unroll
        for (int i = 0; i < 4; i++) {
            __half2 h = __floats2half2_rn(tanh_fast(acc[0][i]), tanh_fast(acc[1][i]));
            g_Hh[((b * WPAD) + w0 + wl + i) * 32 + p] = *(uint32_t*)&h;
        }
    }
}

// ===========================================================================
// Kernel 2: dual GEMM mma.sync fp16 (3x k16 + 1x k8 = K56), ldmatrix loads,
//   3-stage cp.async pipeline over 16 x 64-w stages.
// ===========================================================================
#define ROWB 144    // 72 halves per smem row: conflict-free 16B phases

#define MMA_F16(C, A0, A1, A2, A3, B0, B1)                                  \
    asm volatile(                                                           \
        "mma.sync.aligned.m16n8k16.row.col.f32.f16.f16.f32 "                \
        "{%0,%1,%2,%3}, {%4,%5,%6,%7}, {%8,%9}, {%0,%1,%2,%3};"             \
        : "+f"((C)[0]), "+f"((C)[1]), "+f"((C)[2]), "+f"((C)[3])            \
        : "r"(A0), "r"(A1), "r"(A2), "r"(A3), "r"(B0), "r"(B1))

#define MMA_F16K8(C, A0, A1, B0)                                            \
    asm volatile(                                                           \
        "mma.sync.aligned.m16n8k8.row.col.f32.f16.f16.f32 "                 \
        "{%0,%1,%2,%3}, {%4,%5}, {%6}, {%0,%1,%2,%3};"                      \
        : "+f"((C)[0]), "+f"((C)[1]), "+f"((C)[2]), "+f"((C)[3])            \
        : "r"(A0), "r"(A1), "r"(B0))

#define LDSM_X4(R, A)                                                       \
    asm volatile("ldmatrix.sync.aligned.m8n8.x4.shared.b16 "                \
                 "{%0,%1,%2,%3}, [%4];"                                     \
                 : "=r"((R)[0]), "=r"((R)[1]), "=r"((R)[2]), "=r"((R)[3])   \
                 : "r"(A))

#define LDSM_X1(R, A)                                                       \
    asm volatile("ldmatrix.sync.aligned.m8n8.x1.shared.b16 {%0}, [%1];"     \
                 : "=r"(R) : "r"(A))

#define CP_ASYNC16(S, G)                                                    \
    asm volatile("cp.async.cg.shared.global [%0], [%1], 16;"                \
                 :: "r"(S), "l"(G))
#define CP_COMMIT()  asm volatile("cp.async.commit_group;" ::: "memory")
#define CP_WAIT1()   asm volatile("cp.async.wait_group 1;" ::: "memory")
#define CP_WAIT0()   asm volatile("cp.async.wait_group 0;" ::: "memory")

__device__ __forceinline__ uint32_t packh2(float lo, float hi) {
    __half2 h = __floats2half2_rn(lo, hi);
    return *(uint32_t*)&h;
}
__device__ __forceinline__ float ex2f(float x) {
    float y;
    asm("ex2.approx.f32 %0, %1;" : "=f"(y) : "f"(x));
    return y;
}
__device__ __forceinline__ uint32_t cvta_smem(const void* p) {
    uint32_t a;
    asm("{ .reg .u64 t; cvta.to.shared.u64 t, %1; cvt.u32.u64 %0, t; }"
        : "=r"(a) : "l"(p));
    return a;
}

__device__ __forceinline__ void compute_chunk(
    uint32_t sld, const uint32_t uA[3][4], const uint32_t oA[3][4],
    const uint32_t uA3[2], const uint32_t oA3[2],
    float dacc[2], float nacc[2]) {
    // hoist all 7 ldmatrix up front so LDS latency overlaps the first MMAs
    uint32_t b0v[3][4], b1v[3][4], bt[4];
#pragma unroll
    for (int ks = 0; ks < 3; ks++) {
        LDSM_X4(b0v[ks], sld + ks * 32);
        LDSM_X4(b1v[ks], sld + ks * 32 + 16);
    }
    LDSM_X4(bt, sld + 96);

    float sacc[4][4], pacc[4][4];
#pragma unroll
    for (int nf = 0; nf < 4; nf++)
#pragma unroll
        for (int c = 0; c < 4; c++) { sacc[nf][c] = 0.f; pacc[nf][c] = 0.f; }

#pragma unroll
    for (int ks = 0; ks < 3; ks++)
#pragma unroll
        for (int nf = 0; nf < 4; nf++) {
            MMA_F16(sacc[nf], uA[ks][0], uA[ks][1], uA[ks][2], uA[ks][3],
                    b0v[ks][nf], b1v[ks][nf]);
            MMA_F16(pacc[nf], oA[ks][0], oA[ks][1], oA[ks][2], oA[ks][3],
                    b0v[ks][nf], b1v[ks][nf]);
        }
#pragma unroll
    for (int nf = 0; nf < 4; nf++) {
        MMA_F16K8(sacc[nf], uA3[0], uA3[1], bt[nf]);
        MMA_F16K8(pacc[nf], oA3[0], oA3[1], bt[nf]);
    }
#pragma unroll
    for (int nf = 0; nf < 4; nf++)
#pragma unroll
        for (int c = 0; c < 4; c++) {
            float e = ex2f(sacc[nf][c]);
            int r = c >> 1;
            dacc[r] += e;
            nacc[r] = fmaf(e, pacc[nf][c], nacc[r]);
        }
}

__global__ __launch_bounds__(256, 2)
void attn_kernel(const float* __restrict__ u_w, const float* __restrict__ out_w,
                 const float* __restrict__ out_b, float* __restrict__ out) {
    __shared__ __align__(16) uint32_t Hs[3][64 * 36];   // 3 x 9216B

    const int tid  = threadIdx.x;
    const int b    = blockIdx.y;
    const int l0   = blockIdx.x * 128;
    const int lane = tid & 31;
    const int wid  = tid >> 5;
    const int gid  = lane >> 2;
    const int tig  = lane & 3;

    // ---- Hoisted A fragments: U pre-scaled by log2(e); K56
    const float LOG2E = 1.4426950408889634f;
    uint32_t uA[3][4], oA[3][4], uA3[2], oA3[2];
#pragma unroll
    for (int ks = 0; ks < 3; ks++)
#pragma unroll
        for (int h = 0; h < 2; h++) {
            int kp = ks * 8 + tig + h * 4;
#pragma unroll
            for (int mo = 0; mo < 2; mo++) {
                int l = l0 + wid * 16 + gid + mo * 8;
                float2 uv = make_float2(0.f, 0.f), ov = make_float2(0.f, 0.f);
                if (l < LL) {
                    uv = *(const float2*)&u_w[l * CC + 2 * kp];
                    ov = *(const float2*)&out_w[l * CC + 2 * kp];
                }
                uA[ks][h * 2 + mo] = packh2(uv.x * LOG2E, uv.y * LOG2E);
                oA[ks][h * 2 + mo] = packh2(ov.x, ov.y);
            }
        }
    {
        int kp = 24 + tig;   // only kp 24 (k48,49) non-zero
#pragma unroll
        for (int mo = 0; mo < 2; mo++) {
            int l = l0 + wid * 16 + gid + mo * 8;
            float u0 = 0.f, u1 = 0.f, o0 = 0.f, o1 = 0.f;
            if (l < LL && kp == 24) {
                u0 = u_w[l * CC + 48]; u1 = u_w[l * CC + 49];
                o0 = out_w[l * CC + 48]; o1 = out_w[l * CC + 49];
            }
            uA3[mo] = packh2(u0 * LOG2E, u1 * LOG2E);
            oA3[mo] = packh2(o0, o1);
        }
    }

    // ---- cp.async loader: 256 threads x 2 x 16B = 64 rows x 128B per stage
    const int lrow = tid >> 3, lseg = tid & 7;
    const uint32_t* gsrc = g_Hh + (b * WPAD + lrow) * 32 + lseg * 4;
    uint32_t sb[3];
    sb[0] = cvta_smem(&Hs[0][0]);
    sb[1] = cvta_smem(&Hs[1][0]);
    sb[2] = cvta_smem(&Hs[2][0]);
    const uint32_t stoff0 = lrow * ROWB + lseg * 16;
    const uint32_t stoff1 = (lrow + 32) * ROWB + lseg * 16;

#define ISSUE_STAGE(s)                                                       \
    do {                                                                     \
        const uint32_t* g_ = gsrc + (s) * 64 * 32;                           \
        uint32_t d_ = sb[(s) % 3];                                           \
        CP_ASYNC16(d_ + stoff0, g_);                                         \
        CP_ASYNC16(d_ + stoff1, g_ + 32 * 32);                               \
        CP_COMMIT();                                                         \
    } while (0)

    ISSUE_STAGE(0);
    ISSUE_STAGE(1);
    CP_WAIT1();
    __syncthreads();

    float dacc[2] = {0.f, 0.f}, nacc[2] = {0.f, 0.f};

#pragma unroll 1
    for (int st = 0; st < 15; st++) {
        if (st <= 13) ISSUE_STAGE(st + 2);

        const uint32_t sbase = sb[st % 3];
        compute_chunk(sbase + lane * ROWB, uA, oA, uA3, oA3, dacc, nacc);
        compute_chunk(sbase + (32 + lane) * ROWB, uA, oA, uA3, oA3, dacc, nacc);

        if (st < 14) CP_WAIT1(); else CP_WAIT0();
        __syncthreads();
    }

    // ---- stage 15 (buf 0): w960..991 full; w992..999 -> nf==0 only
    {
        const uint32_t sbase = sb[0];
        compute_chunk(sbase + lane * ROWB, uA, oA, uA3, oA3, dacc, nacc);

        const uint32_t sld = sbase + (32 + (lane & 7)) * ROWB;
        float s4[4] = {0.f, 0.f, 0.f, 0.f}, p4[4] = {0.f, 0.f, 0.f, 0.f};
#pragma unroll
        for (int ks = 0; ks < 3; ks++) {
            uint32_t b0, b1;
            LDSM_X1(b0, sld + ks * 32);
            LDSM_X1(b1, sld + ks * 32 + 16);
            MMA_F16(s4, uA[ks][0], uA[ks][1], uA[ks][2], uA[ks][3], b0, b1);
            MMA_F16(p4, oA[ks][0], oA[ks][1], oA[ks][2], oA[ks][3], b0, b1);
        }
        uint32_t btl;
        LDSM_X1(btl, sld + 96);
        MMA_F16K8(s4, uA3[0], uA3[1], btl);
        MMA_F16K8(p4, oA3[0], oA3[1], btl);
#pragma unroll
        for (int c = 0; c < 4; c++) {
            float e = ex2f(s4[c]);
            int r = c >> 1;
            dacc[r] += e;
            nacc[r] = fmaf(e, p4[c], nacc[r]);
        }
    }

    // ---- reduce over 4 k-group lanes (different w), sigmoid, store
#pragma unroll
    for (int r = 0; r < 2; r++) {
        dacc[r] += __shfl_xor_sync(0xffffffffu, dacc[r], 1);
        dacc[r] += __shfl_xor_sync(0xffffffffu, dacc[r], 2);
        nacc[r] += __shfl_xor_sync(0xffffffffu, nacc[r], 1);
        nacc[r] += __shfl_xor_sync(0xffffffffu, nacc[r], 2);
    }
    if (tig == 0) {
#pragma unroll
        for (int r = 0; r < 2; r++) {
            int l = l0 + wid * 16 + gid + r * 8;
            if (l < LL) {
                float z = nacc[r] / dacc[r] + out_b[l];
                out[b * LL + l] = 1.f / (1.f + __expf(-z));
            }
        }
    }
}

// ===========================================================================
extern "C" void kernel_launch(void* const* d_in, const int* in_sizes, int n_in,
                              void* d_out, int out_size) {
    const int*   x       = (const int*)  d_in[0];
    const float* W_embed = (const float*)d_in[1];
    const float* conv_w  = (const float*)d_in[2];
    const float* conv_b  = (const float*)d_in[3];
    const float* u_w     = (const float*)d_in[4];
    const float* out_w   = (const float*)d_in[5];
    const float* out_b   = (const float*)d_in[6];
    float* out = (float*)d_out;

    dim3 cgrid(WLEN / CT_W, BB);          // (25, 8)
    conv_kernel<<<cgrid, 256>>>(x, W_embed, conv_w, conv_b);

    dim3 agrid((LL + 127) / 128, BB);     // (141, 8)
    attn_kernel<<<agrid, 256>>>(u_w, out_w, out_b, out);
}

// round 11
// speedup vs baseline: 1.0847x; 1.0847x over previous
#include <cuda_runtime.h>
#include <cuda_fp16.h>
#include <math.h>
#include <stdint.h>

#define BB   8
#define WLEN 1000
#define EMB  100
#define CC   50
#define LL   18000

#define WPAD 1024
// H: [b][w][k-halves], 64 halves (128B) per w row; k>=50 and w>=1000 stay zero
__device__ __align__(16) uint32_t g_Hh[BB * WPAD * 32];

// ===========================================================================
// Kernel 1: embedding + conv1d(k=3,same) + tanh -> g_Hh[b][w][k]
// swizzled emb_s: conflict-free LDS/STS
// ===========================================================================
#define CT_W    40
#define CT_ROWS (CT_W + 2)

__device__ __forceinline__ float tanh_fast(float x) {
    float y;
    asm("tanh.approx.f32 %0, %1;" : "=f"(y) : "f"(x));
    return y;
}

__global__ __launch_bounds__(256)
void conv_kernel(const int* __restrict__ x, const float* __restrict__ W_embed,
                 const float* __restrict__ conv_w, const float* __restrict__ conv_b) {
    __shared__ __align__(16) float emb_s[CT_ROWS * 128];
    __shared__ int tok_s[CT_ROWS];
    const int b  = blockIdx.y;
    const int w0 = blockIdx.x * CT_W;
    const int tid = threadIdx.x;

    if (tid < CT_ROWS) {
        int w = w0 - 1 + tid;
        tok_s[tid] = (w >= 0 && w < WLEN) ? x[b * WLEN + w] : -1;
    }
    __syncthreads();
    for (int i = tid; i < CT_ROWS * 25; i += 256) {
        int r = i / 25, g = i - r * 25;
        int t = tok_s[r];
        float4 v = make_float4(0.f, 0.f, 0.f, 0.f);
        if (t >= 0) v = *(const float4*)&W_embed[(long)t * EMB + g * 4];
        *(float4*)&emb_s[(r * 32 + (g ^ ((r >> 2) & 7))) * 4] = v;
    }
    __syncthreads();

    if (tid < 250) {
        const int p = tid / 10, q = tid - p * 10;
        const int wl = q * 4;
        const int sw0 = q & 7, sw1 = (q + 1) & 7;
        const int c0 = 2 * p, c1 = 2 * p + 1;
        float acc[2][4];
        float bias0 = conv_b[c0], bias1 = conv_b[c1];
#pragma unroll
        for (int w = 0; w < 4; w++) { acc[0][w] = bias0; acc[1][w] = bias1; }

        const float4* cw0 = (const float4*)(conv_w + c0 * EMB * 3);
        const float4* cw1 = (const float4*)(conv_w + c1 * EMB * 3);

        for (int g = 0; g < 25; g++) {
            float4 v[6];
#pragma unroll
            for (int r = 0; r < 6; r++) {
                int sw = (r < 4) ? sw0 : sw1;
                v[r] = *(const float4*)&emb_s[((wl + r) * 32 + (g ^ sw)) * 4];
            }
            float4 q0 = cw0[g * 3], q1 = cw0[g * 3 + 1], q2 = cw0[g * 3 + 2];
#pragma unroll
            for (int w = 0; w < 4; w++) {
                acc[0][w] = fmaf(v[w].x, q0.x, acc[0][w]);
                acc[0][w] = fmaf(v[w + 1].x, q0.y, acc[0][w]);
                acc[0][w] = fmaf(v[w + 2].x, q0.z, acc[0][w]);
                acc[0][w] = fmaf(v[w].y, q0.w, acc[0][w]);
                acc[0][w] = fmaf(v[w + 1].y, q1.x, acc[0][w]);
                acc[0][w] = fmaf(v[w + 2].y, q1.y, acc[0][w]);
                acc[0][w] = fmaf(v[w].z, q1.z, acc[0][w]);
                acc[0][w] = fmaf(v[w + 1].z, q1.w, acc[0][w]);
                acc[0][w] = fmaf(v[w + 2].z, q2.x, acc[0][w]);
                acc[0][w] = fmaf(v[w].w, q2.y, acc[0][w]);
                acc[0][w] = fmaf(v[w + 1].w, q2.z, acc[0][w]);
                acc[0][w] = fmaf(v[w + 2].w, q2.w, acc[0][w]);
            }
            q0 = cw1[g * 3]; q1 = cw1[g * 3 + 1]; q2 = cw1[g * 3 + 2];
#pragma unroll
            for (int w = 0; w < 4; w++) {
                acc[1][w] = fmaf(v[w].x, q0.x, acc[1][w]);
                acc[1][w] = fmaf(v[w + 1].x, q0.y, acc[1][w]);
                acc[1][w] = fmaf(v[w + 2].x, q0.z, acc[1][w]);
                acc[1][w] = fmaf(v[w].y, q0.w, acc[1][w]);
                acc[1][w] = fmaf(v[w + 1].y, q1.x, acc[1][w]);
                acc[1][w] = fmaf(v[w + 2].y, q1.y, acc[1][w]);
                acc[1][w] = fmaf(v[w].z, q1.z, acc[1][w]);
                acc[1][w] = fmaf(v[w + 1].z, q1.w, acc[1][w]);
                acc[1][w] = fmaf(v[w + 2].z, q2.x, acc[1][w]);
                acc[1][w] = fmaf(v[w].w, q2.y, acc[1][w]);
                acc[1][w] = fmaf(v[w + 1].w, q2.z, acc[1][w]);
                acc[1][w] = fmaf(v[w + 2].w, q2.w, acc[1][w]);
            }
        }
#pragma unroll
        for (int i = 0; i < 4; i++) {
            __half2 h = __floats2half2_rn(tanh_fast(acc[0][i]), tanh_fast(acc[1][i]));
            g_Hh[((b * WPAD) + w0 + wl + i) * 32 + p] = *(uint32_t*)&h;
        }
    }
}

// ===========================================================================
// Kernel 2: dual GEMM mma.sync fp16 (3x k16 + 1x k8 = K56), ldmatrix loads.
//   SMALL CTA: 128 threads / 4 warps / 64 labels, 5 CTAs/SM -> 5 independent
//   barrier domains per SM. cp.async double-buffered 32-w chunks.
// ===========================================================================
#define ROWB 144    // 72 halves per smem row: conflict-free 16B phases

#define MMA_F16(C, A0, A1, A2, A3, B0, B1)                                  \
    asm volatile(                                                           \
        "mma.sync.aligned.m16n8k16.row.col.f32.f16.f16.f32 "                \
        "{%0,%1,%2,%3}, {%4,%5,%6,%7}, {%8,%9}, {%0,%1,%2,%3};"             \
        : "+f"((C)[0]), "+f"((C)[1]), "+f"((C)[2]), "+f"((C)[3])            \
        : "r"(A0), "r"(A1), "r"(A2), "r"(A3), "r"(B0), "r"(B1))

#define MMA_F16K8(C, A0, A1, B0)                                            \
    asm volatile(                                                           \
        "mma.sync.aligned.m16n8k8.row.col.f32.f16.f16.f32 "                 \
        "{%0,%1,%2,%3}, {%4,%5}, {%6}, {%0,%1,%2,%3};"                      \
        : "+f"((C)[0]), "+f"((C)[1]), "+f"((C)[2]), "+f"((C)[3])            \
        : "r"(A0), "r"(A1), "r"(B0))

#define LDSM_X4(R, A)                                                       \
    asm volatile("ldmatrix.sync.aligned.m8n8.x4.shared.b16 "                \
                 "{%0,%1,%2,%3}, [%4];"                                     \
                 : "=r"((R)[0]), "=r"((R)[1]), "=r"((R)[2]), "=r"((R)[3])   \
                 : "r"(A))

#define LDSM_X1(R, A)                                                       \
    asm volatile("ldmatrix.sync.aligned.m8n8.x1.shared.b16 {%0}, [%1];"     \
                 : "=r"(R) : "r"(A))

#define CP_ASYNC16(S, G)                                                    \
    asm volatile("cp.async.cg.shared.global [%0], [%1], 16;"                \
                 :: "r"(S), "l"(G))
#define CP_COMMIT()  asm volatile("cp.async.commit_group;" ::: "memory")
#define CP_WAIT1()   asm volatile("cp.async.wait_group 1;" ::: "memory")
#define CP_WAIT0()   asm volatile("cp.async.wait_group 0;" ::: "memory")

__device__ __forceinline__ uint32_t packh2(float lo, float hi) {
    __half2 h = __floats2half2_rn(lo, hi);
    return *(uint32_t*)&h;
}
__device__ __forceinline__ float ex2f(float x) {
    float y;
    asm("ex2.approx.f32 %0, %1;" : "=f"(y) : "f"(x));
    return y;
}
__device__ __forceinline__ uint32_t cvta_smem(const void* p) {
    uint32_t a;
    asm("{ .reg .u64 t; cvta.to.shared.u64 t, %1; cvt.u32.u64 %0, t; }"
        : "=r"(a) : "l"(p));
    return a;
}

// per-ks ldmatrix (NOT all hoisted) to keep register count low
__device__ __forceinline__ void compute_chunk(
    uint32_t sld, const uint32_t uA[3][4], const uint32_t oA[3][4],
    const uint32_t uA3[2], const uint32_t oA3[2],
    float dacc[2], float nacc[2]) {
    float sacc[4][4], pacc[4][4];
#pragma unroll
    for (int nf = 0; nf < 4; nf++)
#pragma unroll
        for (int c = 0; c < 4; c++) { sacc[nf][c] = 0.f; pacc[nf][c] = 0.f; }

#pragma unroll
    for (int ks = 0; ks < 3; ks++) {
        uint32_t b0v[4], b1v[4];
        LDSM_X4(b0v, sld + ks * 32);
        LDSM_X4(b1v, sld + ks * 32 + 16);
#pragma unroll
        for (int nf = 0; nf < 4; nf++) {
            MMA_F16(sacc[nf], uA[ks][0], uA[ks][1], uA[ks][2], uA[ks][3],
                    b0v[nf], b1v[nf]);
            MMA_F16(pacc[nf], oA[ks][0], oA[ks][1], oA[ks][2], oA[ks][3],
                    b0v[nf], b1v[nf]);
        }
    }
    {
        uint32_t bt[4];
        LDSM_X4(bt, sld + 96);
#pragma unroll
        for (int nf = 0; nf < 4; nf++) {
            MMA_F16K8(sacc[nf], uA3[0], uA3[1], bt[nf]);
            MMA_F16K8(pacc[nf], oA3[0], oA3[1], bt[nf]);
        }
    }
#pragma unroll
    for (int nf = 0; nf < 4; nf++)
#pragma unroll
        for (int c = 0; c < 4; c++) {
            float e = ex2f(sacc[nf][c]);
            int r = c >> 1;
            dacc[r] += e;
            nacc[r] = fmaf(e, pacc[nf][c], nacc[r]);
        }
}

__global__ __launch_bounds__(128, 5)
void attn_kernel(const float* __restrict__ u_w, const float* __restrict__ out_w,
                 const float* __restrict__ out_b, float* __restrict__ out) {
    __shared__ __align__(16) uint32_t Hs[2][32 * 36];   // 2 x 4608B

    const int tid  = threadIdx.x;
    const int b    = blockIdx.y;
    const int l0   = blockIdx.x * 64;
    const int lane = tid & 31;
    const int wid  = tid >> 5;          // 0..3 label groups
    const int gid  = lane >> 2;
    const int tig  = lane & 3;

    // ---- Hoisted A fragments: U pre-scaled by log2(e); K56
    const float LOG2E = 1.4426950408889634f;
    uint32_t uA[3][4], oA[3][4], uA3[2], oA3[2];
#pragma unroll
    for (int ks = 0; ks < 3; ks++)
#pragma unroll
        for (int h = 0; h < 2; h++) {
            int kp = ks * 8 + tig + h * 4;
#pragma unroll
            for (int mo = 0; mo < 2; mo++) {
                int l = l0 + wid * 16 + gid + mo * 8;
                float2 uv = make_float2(0.f, 0.f), ov = make_float2(0.f, 0.f);
                if (l < LL) {
                    uv = *(const float2*)&u_w[l * CC + 2 * kp];
                    ov = *(const float2*)&out_w[l * CC + 2 * kp];
                }
                uA[ks][h * 2 + mo] = packh2(uv.x * LOG2E, uv.y * LOG2E);
                oA[ks][h * 2 + mo] = packh2(ov.x, ov.y);
            }
        }
    {
        int kp = 24 + tig;   // only kp 24 (k48,49) non-zero
#pragma unroll
        for (int mo = 0; mo < 2; mo++) {
            int l = l0 + wid * 16 + gid + mo * 8;
            float u0 = 0.f, u1 = 0.f, o0 = 0.f, o1 = 0.f;
            if (l < LL && kp == 24) {
                u0 = u_w[l * CC + 48]; u1 = u_w[l * CC + 49];
                o0 = out_w[l * CC + 48]; o1 = out_w[l * CC + 49];
            }
            uA3[mo] = packh2(u0 * LOG2E, u1 * LOG2E);
            oA3[mo] = packh2(o0, o1);
        }
    }

    // ---- cp.async loader: 128 threads x 2 x 16B = 32 rows x 128B per chunk
    const int lrow = tid >> 2;             // 0..31
    const int lseg = (tid & 3) * 2;        // 0,2,4,6  (each thread: 2 segs)
    const uint32_t* gsrc = g_Hh + (b * WPAD + lrow) * 32 + lseg * 4;
    uint32_t sb[2];
    sb[0] = cvta_smem(&Hs[0][0]);
    sb[1] = cvta_smem(&Hs[1][0]);
    const uint32_t stoff = lrow * ROWB + lseg * 16;

#define ISSUE_CHUNK(s)                                                       \
    do {                                                                     \
        const uint32_t* g_ = gsrc + (s) * 32 * 32;                           \
        uint32_t d_ = sb[(s) & 1] + stoff;                                   \
        CP_ASYNC16(d_, g_);                                                  \
        CP_ASYNC16(d_ + 16, g_ + 4);                                         \
        CP_COMMIT();                                                         \
    } while (0)

    ISSUE_CHUNK(0);
    ISSUE_CHUNK(1);
    CP_WAIT1();
    __syncthreads();

    float dacc[2] = {0.f, 0.f}, nacc[2] = {0.f, 0.f};

#pragma unroll 1
    for (int ch = 0; ch < 31; ch++) {
        if (ch <= 29) ISSUE_CHUNK(ch + 2);

        compute_chunk(sb[ch & 1] + lane * ROWB, uA, oA, uA3, oA3, dacc, nacc);

        if (ch < 30) CP_WAIT1(); else CP_WAIT0();
        __syncthreads();
    }

    // ---- chunk 31 (buf1): valid w = 992..999 -> nf==0 only
    {
        const uint32_t sld = sb[1] + (lane & 7) * ROWB;
        float s4[4] = {0.f, 0.f, 0.f, 0.f}, p4[4] = {0.f, 0.f, 0.f, 0.f};
#pragma unroll
        for (int ks = 0; ks < 3; ks++) {
            uint32_t b0, b1;
            LDSM_X1(b0, sld + ks * 32);
            LDSM_X1(b1, sld + ks * 32 + 16);
            MMA_F16(s4, uA[ks][0], uA[ks][1], uA[ks][2], uA[ks][3], b0, b1);
            MMA_F16(p4, oA[ks][0], oA[ks][1], oA[ks][2], oA[ks][3], b0, b1);
        }
        uint32_t btl;
        LDSM_X1(btl, sld + 96);
        MMA_F16K8(s4, uA3[0], uA3[1], btl);
        MMA_F16K8(p4, oA3[0], oA3[1], btl);
#pragma unroll
        for (int c = 0; c < 4; c++) {
            float e = ex2f(s4[c]);
            int r = c >> 1;
            dacc[r] += e;
            nacc[r] = fmaf(e, p4[c], nacc[r]);
        }
    }

    // ---- reduce over 4 k-group lanes (different w), sigmoid, store
#pragma unroll
    for (int r = 0; r < 2; r++) {
        dacc[r] += __shfl_xor_sync(0xffffffffu, dacc[r], 1);
        dacc[r] += __shfl_xor_sync(0xffffffffu, dacc[r], 2);
        nacc[r] += __shfl_xor_sync(0xffffffffu, nacc[r], 1);
        nacc[r] += __shfl_xor_sync(0xffffffffu, nacc[r], 2);
    }
    if (tig == 0) {
#pragma unroll
        for (int r = 0; r < 2; r++) {
            int l = l0 + wid * 16 + gid + r * 8;
            if (l < LL) {
                float z = nacc[r] / dacc[r] + out_b[l];
                out[b * LL + l] = 1.f / (1.f + __expf(-z));
            }
        }
    }
}

// ===========================================================================
extern "C" void kernel_launch(void* const* d_in, const int* in_sizes, int n_in,
                              void* d_out, int out_size) {
    const int*   x       = (const int*)  d_in[0];
    const float* W_embed = (const float*)d_in[1];
    const float* conv_w  = (const float*)d_in[2];
    const float* conv_b  = (const float*)d_in[3];
    const float* u_w     = (const float*)d_in[4];
    const float* out_w   = (const float*)d_in[5];
    const float* out_b   = (const float*)d_in[6];
    float* out = (float*)d_out;

    dim3 cgrid(WLEN / CT_W, BB);          // (25, 8)
    conv_kernel<<<cgrid, 256>>>(x, W_embed, conv_w, conv_b);

    dim3 agrid((LL + 63) / 64, BB);       // (282, 8)
    attn_kernel<<<agrid, 128>>>(u_w, out_w, out_b, out);
}